// round 4
// baseline (speedup 1.0000x reference)
#include <cuda_runtime.h>
#include <math.h>

#define NB 64
#define CC 256
#define TT 64
#define VV 25
#define HID 16
#define NCV (NB*CC)            // 16384 (n,c) chunks
#define CHUNK (TT*VV)          // 1600 floats per (n,c)
#define TOTAL (NB*CC*TT*VV)    // 26214400

#define CPB 2                  // chunks per block (scale + reduce)
#define SCALE_THREADS 256

// scratch (allocation-free rule: __device__ globals)
__device__ float g_avg[NCV];
__device__ float g_mx[NCV];
__device__ float g_gates[NB * 5 * CC];

// output joint -> input joint (TORSO, LEFT_HAND, LEFT_LEG, RIGHT_HAND, RIGHT_LEG)
__constant__ int c_perm[VV] = {0,1,2,3,20,  8,9,10,11,23,24,  16,17,18,19,  4,5,6,7,21,22,  12,13,14,15};
__constant__ int c_grp[VV]  = {0,0,0,0,0,   1,1,1,1,1,1,      2,2,2,2,      3,3,3,3,3,3,    4,4,4,4};

// ---------------- K1: torso mean/max per (n,c), COALESCED via SMEM staging ----------------
// Reads the full array float4-coalesced (we pay for ~all sectors anyway) and warms L2 for K3.
__global__ __launch_bounds__(256) void reduce_kernel(const float* __restrict__ x) {
    __shared__ float sx[CPB * CHUNK];      // 12.8 KB
    __shared__ float ps[8], pm[8];
    const int tid = threadIdx.x;
    const int base = blockIdx.x * CPB;
    const float4* __restrict__ src = reinterpret_cast<const float4*>(x + (size_t)base * CHUNK);

#pragma unroll
    for (int idx = tid; idx < CPB * CHUNK / 4; idx += 256)
        reinterpret_cast<float4*>(sx)[idx] = src[idx];
    __syncthreads();

    const int cl = tid >> 7;               // chunk-local 0..1
    const int r  = tid & 127;
    float s = 0.f, m = -INFINITY;
    if (r < TT) {                          // one t-row per active thread (warps 0,1,4,5)
        const float* row = sx + cl * CHUNK + r * VV;   // stride 25: conflict-free banks
        float v0 = row[0], v1 = row[1], v2 = row[2], v3 = row[3], v4 = row[20];
        s = (v0 + v1) + (v2 + v3) + v4;
        m = fmaxf(fmaxf(v0, v1), fmaxf(fmaxf(v2, v3), v4));
    }
#pragma unroll
    for (int o = 16; o; o >>= 1) {
        s += __shfl_xor_sync(0xffffffffu, s, o);
        m = fmaxf(m, __shfl_xor_sync(0xffffffffu, m, o));
    }
    const int wid = tid >> 5, lane = tid & 31;
    if (lane == 0) { ps[wid] = s; pm[wid] = m; }
    __syncthreads();
    if (tid < CPB) {
        float ss = ps[tid * 4] + ps[tid * 4 + 1];
        float mm = fmaxf(pm[tid * 4], pm[tid * 4 + 1]);
        g_avg[base + tid] = ss * (1.0f / 320.0f);
        g_mx[base + tid]  = mm;
    }
}

// ---------------- K2: per-(n,group) MLP -> gates ----------------
__global__ void mlp_kernel(const float* __restrict__ W1, const float* __restrict__ b1,
                           const float* __restrict__ W2, const float* __restrict__ b2) {
    int blk = blockIdx.x;          // n*5 + f
    int n = blk / 5, f = blk % 5;
    __shared__ float pa[CC], pm[CC], hs[HID];
    int tid = threadIdx.x;
    pa[tid] = g_avg[n * CC + tid];
    pm[tid] = g_mx[n * CC + tid];
    __syncthreads();

    int w = tid >> 5, lane = tid & 31;   // 8 warps, 2 hidden units each
#pragma unroll
    for (int hh = 0; hh < 2; hh++) {
        int h = w * 2 + hh;
        const float* w1row = W1 + (f * HID + h) * CC;
        float sa = 0.f, sm = 0.f;
#pragma unroll
        for (int c = lane; c < CC; c += 32) {
            float wv = w1row[c];
            sa = fmaf(wv, pa[c], sa);
            sm = fmaf(wv, pm[c], sm);
        }
#pragma unroll
        for (int o = 16; o; o >>= 1) {
            sa += __shfl_xor_sync(0xffffffffu, sa, o);
            sm += __shfl_xor_sync(0xffffffffu, sm, o);
        }
        if (lane == 0) {
            float b = b1[f * HID + h];
            hs[h] = fmaxf(sa + b, 0.f) + fmaxf(sm + b, 0.f);
        }
    }
    __syncthreads();

    const float* w2row = W2 + ((size_t)f * CC + tid) * HID;
    float o = 2.0f * b2[f * CC + tid];
#pragma unroll
    for (int h = 0; h < HID; h++) o = fmaf(hs[h], w2row[h], o);
    g_gates[n * (5 * CC) + f * CC + tid] = 1.0f / (1.0f + expf(-o));
}

// ---------------- K3: out[n,c,t,j] = x[n,c,t,perm[j]] * gate[n,grp[j],c] ----------------
// SMEM-staged permutation; SMEM LUTs for perm/gate; streaming stores (__stcs) so the
// output doesn't evict x from L2 (x was warmed by reduce_kernel).
__global__ __launch_bounds__(SCALE_THREADS) void scale_kernel(const float* __restrict__ x,
                                                              float* __restrict__ out) {
    __shared__ float sx[CPB * CHUNK];   // 12.8 KB
    __shared__ float sgate[CPB * 32];
    __shared__ int   sperm[32];
    const int tid = threadIdx.x;
    const int base = blockIdx.x * CPB;
    const float4* __restrict__ src = reinterpret_cast<const float4*>(x + (size_t)base * CHUNK);
    float4* __restrict__ dst = reinterpret_cast<float4*>(out + (size_t)base * CHUNK);

    if (tid < VV) sperm[tid] = c_perm[tid];
    if (tid >= 32 && tid < 32 + CPB * VV) {
        int q = tid - 32, cl = q / VV, j = q - cl * VV;
        int nc = base + cl;
        sgate[cl * 32 + j] = g_gates[(nc >> 8) * (5 * CC) + c_grp[j] * CC + (nc & (CC - 1))];
    }

#pragma unroll
    for (int idx = tid; idx < CPB * CHUNK / 4; idx += SCALE_THREADS) {
        reinterpret_cast<float4*>(sx)[idx] = src[idx];
    }
    __syncthreads();

#pragma unroll
    for (int idx = tid; idx < CPB * CHUNK / 4; idx += SCALE_THREADS) {
        int e0 = idx * 4;
        int cl = e0 / CHUNK;
        int rem = e0 - cl * CHUNK;
        float r[4];
#pragma unroll
        for (int k = 0; k < 4; k++) {
            int e = rem + k;
            int t = e / VV;
            int j = e - t * VV;
            r[k] = sx[cl * CHUNK + t * VV + sperm[j]] * sgate[cl * 32 + j];
        }
        __stcs(&dst[idx], make_float4(r[0], r[1], r[2], r[3]));
    }
}

extern "C" void kernel_launch(void* const* d_in, const int* in_sizes, int n_in,
                              void* d_out, int out_size) {
    const float* x  = (const float*)d_in[0];
    const float* W1 = (const float*)d_in[1];
    const float* b1 = (const float*)d_in[2];
    const float* W2 = (const float*)d_in[3];
    const float* b2 = (const float*)d_in[4];
    float* out = (float*)d_out;

    reduce_kernel<<<NCV / CPB, 256>>>(x);               // 8192 blocks, coalesced, warms L2
    mlp_kernel<<<NB * 5, 256>>>(W1, b1, W2, b2);        // 320 blocks
    scale_kernel<<<NCV / CPB, SCALE_THREADS>>>(x, out); // 8192 blocks
}

// round 5
// speedup vs baseline: 1.1254x; 1.1254x over previous
#include <cuda_runtime.h>
#include <math.h>

#define NB 64
#define CC 256
#define TT 64
#define VV 25
#define HID 16
#define NCV (NB*CC)            // 16384 (n,c) chunks
#define CHUNK (TT*VV)          // 1600 floats per (n,c)
#define TOTAL (NB*CC*TT*VV)    // 26214400

#define CPB 2                  // chunks per block (scale + reduce)
#define SCALE_THREADS 256

// scratch (allocation-free rule: __device__ globals)
__device__ float g_avg[NCV];
__device__ float g_mx[NCV];
__device__ float g_gates[NB * 5 * CC];

// output joint -> input joint (TORSO, LEFT_HAND, LEFT_LEG, RIGHT_HAND, RIGHT_LEG)
__constant__ int c_perm[VV] = {0,1,2,3,20,  8,9,10,11,23,24,  16,17,18,19,  4,5,6,7,21,22,  12,13,14,15};
__constant__ int c_grp[VV]  = {0,0,0,0,0,   1,1,1,1,1,1,      2,2,2,2,      3,3,3,3,3,3,    4,4,4,4};

// ---------------- K1: torso mean/max per (n,c), coalesced via SMEM staging ----------------
__global__ __launch_bounds__(256) void reduce_kernel(const float* __restrict__ x) {
    __shared__ float sx[CPB * CHUNK];      // 12.8 KB
    __shared__ float ps[8], pm[8];
    const int tid = threadIdx.x;
    const int base = blockIdx.x * CPB;
    const float4* __restrict__ src = reinterpret_cast<const float4*>(x + (size_t)base * CHUNK);

#pragma unroll
    for (int idx = tid; idx < CPB * CHUNK / 4; idx += 256)
        reinterpret_cast<float4*>(sx)[idx] = src[idx];
    __syncthreads();

    const int cl = tid >> 7;               // chunk-local 0..1
    const int r  = tid & 127;
    float s = 0.f, m = -INFINITY;
    if (r < TT) {                          // one t-row per active thread
        const float* row = sx + cl * CHUNK + r * VV;   // stride 25: conflict-free banks
        float v0 = row[0], v1 = row[1], v2 = row[2], v3 = row[3], v4 = row[20];
        s = (v0 + v1) + (v2 + v3) + v4;
        m = fmaxf(fmaxf(v0, v1), fmaxf(fmaxf(v2, v3), v4));
    }
#pragma unroll
    for (int o = 16; o; o >>= 1) {
        s += __shfl_xor_sync(0xffffffffu, s, o);
        m = fmaxf(m, __shfl_xor_sync(0xffffffffu, m, o));
    }
    const int wid = tid >> 5, lane = tid & 31;
    if (lane == 0) { ps[wid] = s; pm[wid] = m; }
    __syncthreads();
    if (tid < CPB) {
        float ss = ps[tid * 4] + ps[tid * 4 + 1];
        float mm = fmaxf(pm[tid * 4], pm[tid * 4 + 1]);
        g_avg[base + tid] = ss * (1.0f / 320.0f);
        g_mx[base + tid]  = mm;
    }
}

// ---------------- K2: per-(n,group) MLP -> gates ----------------
__global__ void mlp_kernel(const float* __restrict__ W1, const float* __restrict__ b1,
                           const float* __restrict__ W2, const float* __restrict__ b2) {
    int blk = blockIdx.x;          // n*5 + f
    int n = blk / 5, f = blk % 5;
    __shared__ float pa[CC], pm[CC], hs[HID];
    int tid = threadIdx.x;
    pa[tid] = g_avg[n * CC + tid];
    pm[tid] = g_mx[n * CC + tid];
    __syncthreads();

    int w = tid >> 5, lane = tid & 31;   // 8 warps, 2 hidden units each
#pragma unroll
    for (int hh = 0; hh < 2; hh++) {
        int h = w * 2 + hh;
        const float* w1row = W1 + (f * HID + h) * CC;
        float sa = 0.f, sm = 0.f;
#pragma unroll
        for (int c = lane; c < CC; c += 32) {
            float wv = w1row[c];
            sa = fmaf(wv, pa[c], sa);
            sm = fmaf(wv, pm[c], sm);
        }
#pragma unroll
        for (int o = 16; o; o >>= 1) {
            sa += __shfl_xor_sync(0xffffffffu, sa, o);
            sm = fmaxf(sm, sm);  // keep structure
            sm += __shfl_xor_sync(0xffffffffu, sm, o);
        }
        if (lane == 0) {
            float b = b1[f * HID + h];
            hs[h] = fmaxf(sa + b, 0.f) + fmaxf(sm + b, 0.f);
        }
    }
    __syncthreads();

    const float* w2row = W2 + ((size_t)f * CC + tid) * HID;
    float o = 2.0f * b2[f * CC + tid];
#pragma unroll
    for (int h = 0; h < HID; h++) o = fmaf(hs[h], w2row[h], o);
    g_gates[n * (5 * CC) + f * CC + tid] = 1.0f / (1.0f + expf(-o));
}

// ---------------- K3: out[n,c,t,j] = x[n,c,t,perm[j]] * gate[n,grp[j],c] ----------------
// REVERSED chunk order: reduce_kernel streamed x chunks 0->8191 through L2 (126 MB vs
// x=105 MB); reading LIFO (8191->0) consumes the most-recently-cached lines first.
// __stcs keeps the output write stream evict-first so it doesn't evict x.
__global__ __launch_bounds__(SCALE_THREADS) void scale_kernel(const float* __restrict__ x,
                                                              float* __restrict__ out) {
    __shared__ float sx[CPB * CHUNK];   // 12.8 KB
    __shared__ float sgate[CPB * 32];
    __shared__ int   sperm[32];
    const int tid = threadIdx.x;
    const int base = (gridDim.x - 1 - blockIdx.x) * CPB;   // LIFO vs reduce's stream order
    const float4* __restrict__ src = reinterpret_cast<const float4*>(x + (size_t)base * CHUNK);
    float4* __restrict__ dst = reinterpret_cast<float4*>(out + (size_t)base * CHUNK);

    if (tid < VV) sperm[tid] = c_perm[tid];
    if (tid >= 32 && tid < 32 + CPB * VV) {
        int q = tid - 32, cl = q / VV, j = q - cl * VV;
        int nc = base + cl;
        sgate[cl * 32 + j] = g_gates[(nc >> 8) * (5 * CC) + c_grp[j] * CC + (nc & (CC - 1))];
    }

#pragma unroll
    for (int idx = tid; idx < CPB * CHUNK / 4; idx += SCALE_THREADS) {
        reinterpret_cast<float4*>(sx)[idx] = src[idx];
    }
    __syncthreads();

#pragma unroll
    for (int idx = tid; idx < CPB * CHUNK / 4; idx += SCALE_THREADS) {
        int e0 = idx * 4;
        int cl = e0 / CHUNK;
        int rem = e0 - cl * CHUNK;
        float r[4];
#pragma unroll
        for (int k = 0; k < 4; k++) {
            int e = rem + k;
            int t = e / VV;
            int j = e - t * VV;
            r[k] = sx[cl * CHUNK + t * VV + sperm[j]] * sgate[cl * 32 + j];
        }
        __stcs(&dst[idx], make_float4(r[0], r[1], r[2], r[3]));
    }
}

extern "C" void kernel_launch(void* const* d_in, const int* in_sizes, int n_in,
                              void* d_out, int out_size) {
    const float* x  = (const float*)d_in[0];
    const float* W1 = (const float*)d_in[1];
    const float* b1 = (const float*)d_in[2];
    const float* W2 = (const float*)d_in[3];
    const float* b2 = (const float*)d_in[4];
    float* out = (float*)d_out;

    reduce_kernel<<<NCV / CPB, 256>>>(x);               // 8192 blocks, streams x into L2
    mlp_kernel<<<NB * 5, 256>>>(W1, b1, W2, b2);        // 320 blocks
    scale_kernel<<<NCV / CPB, SCALE_THREADS>>>(x, out); // 8192 blocks, reversed order
}